// round 14
// baseline (speedup 1.0000x reference)
#include <cuda_runtime.h>
#include <cuda_bf16.h>
#include <cuda_fp16.h>
#include <cstdint>

#define NB 2
#define NS 4096
#define ND 512
#define NH 8
#define DK 64

#define QSCALE 0.1803368867f

// ---------------- scratch ----------------
__device__ __align__(128) __half g_q16[(size_t)NB*NH*NS*DK];
__device__ __align__(128) __half g_k16[(size_t)NB*NH*NS*DK];
__device__ __align__(128) __half g_v16[(size_t)NB*NH*DK*NS];
__device__ __align__(128) __half g_xh[(size_t)NB*NS*ND];
__device__ __align__(128) __half g_xl[(size_t)NB*NS*ND];
__device__ __align__(128) __half g_wt16[(size_t)24*DK*ND];

// ---------------------------- helpers ----------------------------------
__device__ __forceinline__ uint32_t smem_u32(const void* p) {
    uint32_t a;
    asm("{ .reg .u64 t; cvta.to.shared.u64 t, %1; cvt.u32.u64 %0, t; }" : "=r"(a) : "l"(p));
    return a;
}
__device__ __forceinline__ float ex2f(float x) {
    float y; asm("ex2.approx.f32 %0, %1;" : "=f"(y) : "f"(x)); return y;
}
__device__ __forceinline__ void cpa16(uint32_t dst, const void* src) {
    asm volatile("cp.async.cg.shared.global [%0], [%1], 16;" :: "r"(dst), "l"(src));
}
__device__ __forceinline__ void cp_commit() { asm volatile("cp.async.commit_group;" ::: "memory"); }
template<int N> __device__ __forceinline__ void cp_wait() {
    asm volatile("cp.async.wait_group %0;" :: "n"(N) : "memory");
}

__device__ __forceinline__ void ldsm_x4(uint32_t& r0, uint32_t& r1, uint32_t& r2, uint32_t& r3, uint32_t addr) {
    asm volatile("ldmatrix.sync.aligned.m8n8.x4.shared.b16 {%0,%1,%2,%3}, [%4];"
                 : "=r"(r0), "=r"(r1), "=r"(r2), "=r"(r3) : "r"(addr));
}
__device__ __forceinline__ void mma_hf(float* c, const uint32_t* a, uint32_t b0, uint32_t b1) {
    asm volatile("mma.sync.aligned.m16n8k16.row.col.f32.f16.f16.f32 "
                 "{%0,%1,%2,%3}, {%4,%5,%6,%7}, {%8,%9}, {%0,%1,%2,%3};"
                 : "+f"(c[0]), "+f"(c[1]), "+f"(c[2]), "+f"(c[3])
                 : "r"(a[0]), "r"(a[1]), "r"(a[2]), "r"(a[3]), "r"(b0), "r"(b1));
}
__device__ __forceinline__ void mma_hf_z(float* c, const uint32_t* a, uint32_t b0, uint32_t b1) {
    asm volatile("mma.sync.aligned.m16n8k16.row.col.f32.f16.f16.f32 "
                 "{%0,%1,%2,%3}, {%4,%5,%6,%7}, {%8,%9}, {%10,%11,%12,%13};"
                 : "=f"(c[0]), "=f"(c[1]), "=f"(c[2]), "=f"(c[3])
                 : "r"(a[0]), "r"(a[1]), "r"(a[2]), "r"(a[3]), "r"(b0), "r"(b1),
                   "f"(0.f), "f"(0.f), "f"(0.f), "f"(0.f));
}
__device__ __forceinline__ uint32_t pack2h(float lo, float hi) {
    __half2 t = __float22half2_rn(make_float2(lo, hi));
    return *reinterpret_cast<uint32_t*>(&t);
}
__device__ __forceinline__ float2 unpack2h(uint32_t u) {
    __half2 t = *reinterpret_cast<__half2*>(&u);
    return __half22float2(t);
}

#define ONES2 0x3C003C00u

// ---------------------------------------------------------------------------
// split_x: x fp32 -> fp16 hi/lo
// ---------------------------------------------------------------------------
__global__ __launch_bounds__(256) void split_x(const float* __restrict__ x)
{
    size_t i0 = ((size_t)blockIdx.x * 256 + threadIdx.x) * 4;
    float4 v = *(const float4*)(x + i0);
    float f[4] = {v.x, v.y, v.z, v.w};
    uint32_t h[2], l[2];
    #pragma unroll
    for (int p = 0; p < 2; p++) {
        float a = f[2*p], bq = f[2*p+1];
        uint32_t hp = pack2h(a, bq);
        float2 ff = unpack2h(hp);
        h[p] = hp;
        l[p] = pack2h(a - ff.x, bq - ff.y);
    }
    *(uint2*)(g_xh + i0) = make_uint2(h[0], h[1]);
    *(uint2*)(g_xl + i0) = make_uint2(l[0], l[1]);
}

// ---------------------------------------------------------------------------
// split_w: transpose to [mh][64][512] fp16
// ---------------------------------------------------------------------------
__global__ __launch_bounds__(256) void split_w(
    const float* __restrict__ Wq, const float* __restrict__ Wk, const float* __restrict__ Wv)
{
    __shared__ float Ws[64 * 65];
    const int mh = blockIdx.x;
    const int mat = mh >> 3, h = mh & 7;
    const float* W = ((mat == 0) ? Wq : (mat == 1) ? Wk : Wv) + (size_t)h * ND * DK;
    const int tid = threadIdx.x;

    for (int d0 = 0; d0 < ND; d0 += 64) {
        __syncthreads();
        #pragma unroll
        for (int i = 0; i < 16; i++) {
            int idx = tid + i * 256;
            int r = idx >> 6, n = idx & 63;
            Ws[n * 65 + r] = W[(size_t)(d0 + r) * DK + n];
        }
        __syncthreads();
        #pragma unroll
        for (int i = 0; i < 16; i++) {
            int idx = tid + i * 256;
            int n = idx >> 6, r = idx & 63;
            g_wt16[((size_t)mh * DK + n) * ND + d0 + r] = __float2half_rn(Ws[n * 65 + r]);
        }
    }
}

// ---------------------------------------------------------------------------
// proj_mma: fp16 2-product GEMM (unchanged)
// ---------------------------------------------------------------------------
#define PITCH 144
#define PJ_XH 0
#define PJ_XL 18432
#define PJ_W  36864
#define PJ_STG 46080
#define PJ_SMEM (2 * PJ_STG)

__global__ __launch_bounds__(256, 2) void proj_mma(
    const float* __restrict__ bq, const float* __restrict__ bk, const float* __restrict__ bv)
{
    extern __shared__ char sm[];
    const uint32_t sbase = smem_u32(sm);
    const int tid = threadIdx.x, wid = tid >> 5, lane = tid & 31;
    const int s0 = blockIdx.x * 128;
    const int mh = blockIdx.y;
    const int mat = mh >> 3, h = mh & 7;
    const int b = blockIdx.z;
    const size_t hb = (size_t)b * NH + h;

    const size_t xoff = ((size_t)b * NS + s0) * ND;

    auto pj_load = [&](int c, int st) {
        #pragma unroll
        for (int i = 0; i < 10; i++) {
            int idx = tid + i * 256;
            uint32_t dst; const __half* src;
            if (idx < 2048) {
                int arr = idx >> 10, rem = idx & 1023;
                int row = rem >> 3, ch = rem & 7;
                src = (arr ? g_xl : g_xh) + xoff + (size_t)row * ND + c * 64 + ch * 8;
                dst = sbase + st * PJ_STG + (arr ? PJ_XL : PJ_XH) + row * PITCH + ch * 16;
            } else {
                int i2 = idx - 2048;
                int n = i2 >> 3, ch = i2 & 7;
                src = g_wt16 + ((size_t)mh * DK + n) * ND + c * 64 + ch * 8;
                dst = sbase + st * PJ_STG + PJ_W + n * PITCH + ch * 16;
            }
            cpa16(dst, src);
        }
        cp_commit();
    };

    pj_load(0, 0);

    const int qrow = wid * 16 + (lane & 15);
    const int qcol8 = 8 * (lane >> 4);
    const int brow = (lane & 7) + ((lane >> 4) << 3);
    const int bcol8 = 8 * ((lane >> 3) & 1);

    float acc[8][4] = {};

    for (int c = 0; c < 8; c++) {
        cp_wait<0>();
        __syncthreads();
        if (c + 1 < 8) pj_load(c + 1, (c + 1) & 1);

        const uint32_t sb = sbase + (uint32_t)(c & 1) * PJ_STG;
        uint32_t ah[4][4], al[4][4];
        #pragma unroll
        for (int kb = 0; kb < 4; kb++) {
            uint32_t off = (uint32_t)qrow * PITCH + (uint32_t)(kb * 16 + qcol8) * 2;
            ldsm_x4(ah[kb][0], ah[kb][1], ah[kb][2], ah[kb][3], sb + PJ_XH + off);
            ldsm_x4(al[kb][0], al[kb][1], al[kb][2], al[kb][3], sb + PJ_XL + off);
        }
        #pragma unroll
        for (int kb = 0; kb < 4; kb++) {
            #pragma unroll
            for (int ng = 0; ng < 4; ng++) {
                uint32_t off = (uint32_t)(ng * 16 + brow) * PITCH + (uint32_t)(kb * 16 + bcol8) * 2;
                uint32_t w0, w1, w2, w3;
                ldsm_x4(w0, w1, w2, w3, sb + PJ_W + off);
                mma_hf(acc[2 * ng],     ah[kb], w0, w1);
                mma_hf(acc[2 * ng + 1], ah[kb], w2, w3);
                mma_hf(acc[2 * ng],     al[kb], w0, w1);
                mma_hf(acc[2 * ng + 1], al[kb], w2, w3);
            }
        }
    }

    const float* bias = ((mat == 0) ? bq : (mat == 1) ? bk : bv) + h * DK;
    const int g = lane >> 2, t4 = lane & 3;
    const int r0g = wid * 16 + g;

    if (mat < 2) {
        __half* dq = (mat == 0) ? g_q16 : g_k16;
        const float sc = (mat == 0) ? QSCALE : 1.0f;
        #pragma unroll
        for (int nb = 0; nb < 8; nb++) {
            int col = 8 * nb + 2 * t4;
            float b0 = bias[col], b1 = bias[col + 1];
            #pragma unroll
            for (int half = 0; half < 2; half++) {
                float v0 = (acc[nb][2 * half]     + b0) * sc;
                float v1 = (acc[nb][2 * half + 1] + b1) * sc;
                size_t oi = (hb * NS + s0 + r0g + half * 8) * DK + col;
                *(uint32_t*)(dq + oi) = pack2h(v0, v1);
            }
        }
    } else {
        __half* Vst = (__half*)(sm);
        __syncthreads();
        #pragma unroll
        for (int nb = 0; nb < 8; nb++) {
            int col = 8 * nb + 2 * t4;
            float b0 = bias[col], b1 = bias[col + 1];
            #pragma unroll
            for (int half = 0; half < 2; half++) {
                float v0 = acc[nb][2 * half]     + b0;
                float v1 = acc[nb][2 * half + 1] + b1;
                int srow = r0g + half * 8;
                Vst[col * 136 + srow]       = __float2half_rn(v0);
                Vst[(col + 1) * 136 + srow] = __float2half_rn(v1);
            }
        }
        __syncthreads();
        const int n = tid >> 2, seg = tid & 3;
        const __half* sr = Vst + n * 136 + seg * 32;
        __half* ds = g_v16 + (hb * DK + n) * NS + s0 + seg * 32;
        #pragma unroll
        for (int u = 0; u < 4; u++)
            *(uint4*)(ds + u * 8) = *(const uint4*)(sr + u * 8);
    }
}

// ---------------------------------------------------------------------------
// attn: m32 warp tiles, 3-stage K/V rings, one sync/tile,
// CHUNK-PIPELINED: qk(c+1) issued before softmax(c)+pv(c).
// ---------------------------------------------------------------------------
#define ARR_B  (64 * PITCH)              // 9216
#define Q_B    (128 * PITCH)             // 18432
#define SM_Q   0
#define SM_K   Q_B                       // 3 stages
#define SM_V   (Q_B + 3 * ARR_B)         // 3 stages
#define ATT_SMEM (Q_B + 6 * ARR_B)       // 73728
#define NT (NS / 64)

__global__ __launch_bounds__(128, 2) void attn_mma(float* __restrict__ out)
{
    extern __shared__ char sm[];
    const uint32_t sbase = smem_u32(sm);
    const int tid = threadIdx.x, wid = tid >> 5, lane = tid & 31;
    const int qt = blockIdx.x, h = blockIdx.y, b = blockIdx.z;
    const size_t hb = (size_t)b * NH + h;

    const __half* qp = g_q16 + hb * NS * DK;
    const __half* kp = g_k16 + hb * NS * DK;
    const __half* vp = g_v16 + hb * DK * NS;

    auto loadK = [&](int st, int t) {
        if (t < NT) {
            int j0 = t * 64;
            #pragma unroll
            for (int i = 0; i < 4; i++) {
                int idx = tid + i * 128;
                int row = idx >> 3, ch = idx & 7;
                uint32_t dst = sbase + SM_K + st * ARR_B + row * PITCH + ch * 16;
                cpa16(dst, kp + (size_t)(j0 + row) * DK + ch * 8);
            }
        }
        cp_commit();
    };
    auto loadV = [&](int st, int t) {
        if (t < NT) {
            int j0 = t * 64;
            #pragma unroll
            for (int i = 0; i < 4; i++) {
                int idx = tid + i * 128;
                int row = idx >> 3, ch = idx & 7;
                uint32_t dst = sbase + SM_V + st * ARR_B + row * PITCH + ch * 16;
                cpa16(dst, vp + (size_t)row * NS + j0 + ch * 8);
            }
        }
        cp_commit();
    };

    // prologue: G0 = Q + K0 + V0; then K1 (G1), V1 (G2)
    #pragma unroll
    for (int i = 0; i < 8; i++) {
        int idx = tid + i * 128;
        int row = idx >> 3, ch = idx & 7;
        cpa16(sbase + SM_Q + row * PITCH + ch * 16, qp + (size_t)(qt * 128 + row) * DK + ch * 8);
    }
    #pragma unroll
    for (int i = 0; i < 4; i++) {
        int idx = tid + i * 128;
        int row = idx >> 3, ch = idx & 7;
        cpa16(sbase + SM_K + row * PITCH + ch * 16, kp + (size_t)row * DK + ch * 8);
        cpa16(sbase + SM_V + row * PITCH + ch * 16, vp + (size_t)row * NS + ch * 8);
    }
    cp_commit();            // G0
    loadK(1, 1);            // G1
    loadV(1, 1);            // G2

    cp_wait<2>();
    __syncthreads();

    uint32_t qf[4][8];
    {
        const int qr = wid * 32 + (lane & 15);
        const int qcol8 = 8 * (lane >> 4);
        #pragma unroll
        for (int kb = 0; kb < 4; kb++) {
            uint32_t off0 = (uint32_t)qr * PITCH + (uint32_t)(kb * 16 + qcol8) * 2;
            uint32_t off1 = (uint32_t)(qr + 16) * PITCH + (uint32_t)(kb * 16 + qcol8) * 2;
            ldsm_x4(qf[kb][0], qf[kb][1], qf[kb][2], qf[kb][3], sbase + SM_Q + off0);
            ldsm_x4(qf[kb][4], qf[kb][5], qf[kb][6], qf[kb][7], sbase + SM_Q + off1);
        }
    }

    const int brow = (lane & 7) + ((lane >> 4) << 3);
    const int bcol8 = 8 * ((lane >> 3) & 1);

    float oacc[2][8][4] = {};
    float lacc[2][4] = {};
    float sacc[2][8][4];

    auto kstg = [&](int st) -> uint32_t { return sbase + SM_K + (uint32_t)st * ARR_B; };
    auto vstg = [&](int st) -> uint32_t { return sbase + SM_V + (uint32_t)st * ARR_B; };

    // QK for S column-chunk c (ng = c), all 4 kb reduction steps.
    auto qk_chunk = [&](int c, uint32_t stgK) {
        #pragma unroll
        for (int kb = 0; kb < 4; kb++) {
            uint32_t off = (uint32_t)(c * 16 + brow) * PITCH + (uint32_t)(kb * 16 + bcol8) * 2;
            uint32_t k0, k1, k2, k3;
            ldsm_x4(k0, k1, k2, k3, stgK + off);
            if (kb == 0) {
                mma_hf_z(sacc[0][2 * c],     qf[kb],     k0, k1);
                mma_hf_z(sacc[0][2 * c + 1], qf[kb],     k2, k3);
                mma_hf_z(sacc[1][2 * c],     qf[kb] + 4, k0, k1);
                mma_hf_z(sacc[1][2 * c + 1], qf[kb] + 4, k2, k3);
            } else {
                mma_hf(sacc[0][2 * c],     qf[kb],     k0, k1);
                mma_hf(sacc[0][2 * c + 1], qf[kb],     k2, k3);
                mma_hf(sacc[1][2 * c],     qf[kb] + 4, k0, k1);
                mma_hf(sacc[1][2 * c + 1], qf[kb] + 4, k2, k3);
            }
        }
    };

    // softmax + PV for chunk c (t-chunk = c): consumes sacc[.][2c],[2c+1]
    auto spv_chunk = [&](int c, uint32_t stgV) {
        uint32_t a0[4], a1[4];
        #pragma unroll
        for (int q2 = 0; q2 < 2; q2++) {
            float* c0 = sacc[0][2 * c + q2];
            float* c1 = sacc[1][2 * c + q2];
            c0[0] = ex2f(c0[0]); c0[1] = ex2f(c0[1]); c0[2] = ex2f(c0[2]); c0[3] = ex2f(c0[3]);
            c1[0] = ex2f(c1[0]); c1[1] = ex2f(c1[1]); c1[2] = ex2f(c1[2]); c1[3] = ex2f(c1[3]);
            a0[q2 * 2 + 0] = pack2h(c0[0], c0[1]);
            a0[q2 * 2 + 1] = pack2h(c0[2], c0[3]);
            a1[q2 * 2 + 0] = pack2h(c1[0], c1[1]);
            a1[q2 * 2 + 1] = pack2h(c1[2], c1[3]);
        }
        mma_hf(lacc[0], a0, ONES2, ONES2);
        mma_hf(lacc[1], a1, ONES2, ONES2);
        #pragma unroll
        for (int ng = 0; ng < 4; ng++) {
            uint32_t off = (uint32_t)(ng * 16 + brow) * PITCH + (uint32_t)(c * 16 + bcol8) * 2;
            uint32_t v0, v1, v2, v3;
            ldsm_x4(v0, v1, v2, v3, stgV + off);
            mma_hf(oacc[0][2 * ng],     a0, v0, v1);
            mma_hf(oacc[0][2 * ng + 1], a0, v2, v3);
            mma_hf(oacc[1][2 * ng],     a1, v0, v1);
            mma_hf(oacc[1][2 * ng + 1], a1, v2, v3);
        }
    };

    #pragma unroll 1
    for (int j = 0; j < NT; j++) {
        const int st = j % 3;
        cp_wait<2>();
        __syncthreads();
        loadK((j + 2) % 3, j + 2);
        loadV((j + 2) % 3, j + 2);

        const uint32_t sk = kstg(st), sv = vstg(st);
        qk_chunk(0, sk);
        #pragma unroll
        for (int c = 0; c < 4; c++) {
            if (c < 3) qk_chunk(c + 1, sk);
            spv_chunk(c, sv);
        }
    }
    cp_wait<0>();

    // epilogue
    const int g = lane >> 2, t4 = lane & 3;
    const int rbase = qt * 128 + wid * 32 + g;
    float inv[4] = {1.f / lacc[0][0], 1.f / lacc[0][2], 1.f / lacc[1][0], 1.f / lacc[1][2]};
    #pragma unroll
    for (int rg = 0; rg < 4; rg++) {
        const int mh2 = rg >> 1, lo = rg & 1;
        float* op = out + ((size_t)b * NS + rbase + mh2 * 16 + lo * 8) * (NH * DK) + h * DK;
        #pragma unroll
        for (int nb = 0; nb < 8; nb++) {
            int col = 8 * nb + 2 * t4;
            *(float2*)(op + col) = make_float2(oacc[mh2][nb][2 * lo]     * inv[rg],
                                               oacc[mh2][nb][2 * lo + 1] * inv[rg]);
        }
    }
}

extern "C" void kernel_launch(void* const* d_in, const int* in_sizes, int n_in,
                              void* d_out, int out_size)
{
    const float* x  = (const float*)d_in[0];
    const float* Wq = (const float*)d_in[1];
    const float* Wk = (const float*)d_in[2];
    const float* Wv = (const float*)d_in[3];
    const float* bq = (const float*)d_in[4];
    const float* bk = (const float*)d_in[5];
    const float* bv = (const float*)d_in[6];
    float* out = (float*)d_out;

    split_x<<<(NB * NS * ND) / 1024, 256>>>(x);
    split_w<<<24, 256>>>(Wq, Wk, Wv);

    cudaFuncSetAttribute(proj_mma, cudaFuncAttributeMaxDynamicSharedMemorySize, PJ_SMEM);
    dim3 pgrid(NS / 128, 24, NB);
    proj_mma<<<pgrid, 256, PJ_SMEM>>>(bq, bk, bv);

    cudaFuncSetAttribute(attn_mma, cudaFuncAttributeMaxDynamicSharedMemorySize, ATT_SMEM);
    dim3 agrid(NS / 128, NH, NB);
    attn_mma<<<agrid, 128, ATT_SMEM>>>(out);
}

// round 15
// speedup vs baseline: 1.1527x; 1.1527x over previous
#include <cuda_runtime.h>
#include <cuda_bf16.h>
#include <cuda_fp16.h>
#include <cstdint>

#define NB 2
#define NS 4096
#define ND 512
#define NH 8
#define DK 64

#define QSCALE 0.1803368867f

// ---------------- scratch ----------------
__device__ __align__(128) __half g_q16[(size_t)NB*NH*NS*DK];
__device__ __align__(128) __half g_k16[(size_t)NB*NH*NS*DK];
__device__ __align__(128) __half g_v16[(size_t)NB*NH*DK*NS];
__device__ __align__(128) __half g_x16[(size_t)NB*NS*ND];
__device__ __align__(128) __half g_wt16[(size_t)24*DK*ND];

// ---------------------------- helpers ----------------------------------
__device__ __forceinline__ uint32_t smem_u32(const void* p) {
    uint32_t a;
    asm("{ .reg .u64 t; cvta.to.shared.u64 t, %1; cvt.u32.u64 %0, t; }" : "=r"(a) : "l"(p));
    return a;
}
__device__ __forceinline__ float ex2f(float x) {
    float y; asm("ex2.approx.f32 %0, %1;" : "=f"(y) : "f"(x)); return y;
}
__device__ __forceinline__ void cpa16(uint32_t dst, const void* src) {
    asm volatile("cp.async.cg.shared.global [%0], [%1], 16;" :: "r"(dst), "l"(src));
}
__device__ __forceinline__ void cp_commit() { asm volatile("cp.async.commit_group;" ::: "memory"); }
template<int N> __device__ __forceinline__ void cp_wait() {
    asm volatile("cp.async.wait_group %0;" :: "n"(N) : "memory");
}

__device__ __forceinline__ void ldsm_x4(uint32_t& r0, uint32_t& r1, uint32_t& r2, uint32_t& r3, uint32_t addr) {
    asm volatile("ldmatrix.sync.aligned.m8n8.x4.shared.b16 {%0,%1,%2,%3}, [%4];"
                 : "=r"(r0), "=r"(r1), "=r"(r2), "=r"(r3) : "r"(addr));
}
__device__ __forceinline__ void mma_hf(float* c, const uint32_t* a, uint32_t b0, uint32_t b1) {
    asm volatile("mma.sync.aligned.m16n8k16.row.col.f32.f16.f16.f32 "
                 "{%0,%1,%2,%3}, {%4,%5,%6,%7}, {%8,%9}, {%0,%1,%2,%3};"
                 : "+f"(c[0]), "+f"(c[1]), "+f"(c[2]), "+f"(c[3])
                 : "r"(a[0]), "r"(a[1]), "r"(a[2]), "r"(a[3]), "r"(b0), "r"(b1));
}
__device__ __forceinline__ void mma_hf_z(float* c, const uint32_t* a, uint32_t b0, uint32_t b1) {
    asm volatile("mma.sync.aligned.m16n8k16.row.col.f32.f16.f16.f32 "
                 "{%0,%1,%2,%3}, {%4,%5,%6,%7}, {%8,%9}, {%10,%11,%12,%13};"
                 : "=f"(c[0]), "=f"(c[1]), "=f"(c[2]), "=f"(c[3])
                 : "r"(a[0]), "r"(a[1]), "r"(a[2]), "r"(a[3]), "r"(b0), "r"(b1),
                   "f"(0.f), "f"(0.f), "f"(0.f), "f"(0.f));
}
__device__ __forceinline__ uint32_t pack2h(float lo, float hi) {
    __half2 t = __float22half2_rn(make_float2(lo, hi));
    return *reinterpret_cast<uint32_t*>(&t);
}

#define ONES2 0x3C003C00u

// ---------------------------------------------------------------------------
// split_x: x fp32 -> fp16
// ---------------------------------------------------------------------------
__global__ __launch_bounds__(256) void split_x(const float* __restrict__ x)
{
    size_t i0 = ((size_t)blockIdx.x * 256 + threadIdx.x) * 4;
    float4 v = *(const float4*)(x + i0);
    uint2 o;
    o.x = pack2h(v.x, v.y);
    o.y = pack2h(v.z, v.w);
    *(uint2*)(g_x16 + i0) = o;
}

// ---------------------------------------------------------------------------
// split_w: transpose to [mh][64][512] fp16
// ---------------------------------------------------------------------------
__global__ __launch_bounds__(256) void split_w(
    const float* __restrict__ Wq, const float* __restrict__ Wk, const float* __restrict__ Wv)
{
    __shared__ float Ws[64 * 65];
    const int mh = blockIdx.x;
    const int mat = mh >> 3, h = mh & 7;
    const float* W = ((mat == 0) ? Wq : (mat == 1) ? Wk : Wv) + (size_t)h * ND * DK;
    const int tid = threadIdx.x;

    for (int d0 = 0; d0 < ND; d0 += 64) {
        __syncthreads();
        #pragma unroll
        for (int i = 0; i < 16; i++) {
            int idx = tid + i * 256;
            int r = idx >> 6, n = idx & 63;
            Ws[n * 65 + r] = W[(size_t)(d0 + r) * DK + n];
        }
        __syncthreads();
        #pragma unroll
        for (int i = 0; i < 16; i++) {
            int idx = tid + i * 256;
            int n = idx >> 6, r = idx & 63;
            g_wt16[((size_t)mh * DK + n) * ND + d0 + r] = __float2half_rn(Ws[n * 65 + r]);
        }
    }
}

// ---------------------------------------------------------------------------
// proj_mma: fp16 1-product GEMM (x16 x W16). 128 s x 64 n per CTA.
// ---------------------------------------------------------------------------
#define PITCH 144
#define PJ_X  0
#define PJ_W  18432
#define PJ_STG 27648
#define PJ_SMEM (2 * PJ_STG)

__global__ __launch_bounds__(256, 2) void proj_mma(
    const float* __restrict__ bq, const float* __restrict__ bk, const float* __restrict__ bv)
{
    extern __shared__ char sm[];
    const uint32_t sbase = smem_u32(sm);
    const int tid = threadIdx.x, wid = tid >> 5, lane = tid & 31;
    const int s0 = blockIdx.x * 128;
    const int mh = blockIdx.y;
    const int mat = mh >> 3, h = mh & 7;
    const int b = blockIdx.z;
    const size_t hb = (size_t)b * NH + h;

    const size_t xoff = ((size_t)b * NS + s0) * ND;

    auto pj_load = [&](int c, int st) {
        #pragma unroll
        for (int i = 0; i < 6; i++) {
            int idx = tid + i * 256;            // [0, 1536)
            uint32_t dst; const __half* src;
            if (idx < 1024) {
                int row = idx >> 3, ch = idx & 7;
                src = g_x16 + xoff + (size_t)row * ND + c * 64 + ch * 8;
                dst = sbase + st * PJ_STG + PJ_X + row * PITCH + ch * 16;
            } else {
                int i2 = idx - 1024;            // [0, 512)
                int n = i2 >> 3, ch = i2 & 7;
                src = g_wt16 + ((size_t)mh * DK + n) * ND + c * 64 + ch * 8;
                dst = sbase + st * PJ_STG + PJ_W + n * PITCH + ch * 16;
            }
            cpa16(dst, src);
        }
        cp_commit();
    };

    pj_load(0, 0);

    const int qrow = wid * 16 + (lane & 15);
    const int qcol8 = 8 * (lane >> 4);
    const int brow = (lane & 7) + ((lane >> 4) << 3);
    const int bcol8 = 8 * ((lane >> 3) & 1);

    float acc[8][4] = {};

    for (int c = 0; c < 8; c++) {
        cp_wait<0>();
        __syncthreads();
        if (c + 1 < 8) pj_load(c + 1, (c + 1) & 1);

        const uint32_t sb = sbase + (uint32_t)(c & 1) * PJ_STG;
        uint32_t ah[4][4];
        #pragma unroll
        for (int kb = 0; kb < 4; kb++) {
            uint32_t off = (uint32_t)qrow * PITCH + (uint32_t)(kb * 16 + qcol8) * 2;
            ldsm_x4(ah[kb][0], ah[kb][1], ah[kb][2], ah[kb][3], sb + PJ_X + off);
        }
        #pragma unroll
        for (int kb = 0; kb < 4; kb++) {
            #pragma unroll
            for (int ng = 0; ng < 4; ng++) {
                uint32_t off = (uint32_t)(ng * 16 + brow) * PITCH + (uint32_t)(kb * 16 + bcol8) * 2;
                uint32_t w0, w1, w2, w3;
                ldsm_x4(w0, w1, w2, w3, sb + PJ_W + off);
                mma_hf(acc[2 * ng],     ah[kb], w0, w1);
                mma_hf(acc[2 * ng + 1], ah[kb], w2, w3);
            }
        }
    }

    const float* bias = ((mat == 0) ? bq : (mat == 1) ? bk : bv) + h * DK;
    const int g = lane >> 2, t4 = lane & 3;
    const int r0g = wid * 16 + g;

    if (mat < 2) {
        __half* dq = (mat == 0) ? g_q16 : g_k16;
        const float sc = (mat == 0) ? QSCALE : 1.0f;
        #pragma unroll
        for (int nb = 0; nb < 8; nb++) {
            int col = 8 * nb + 2 * t4;
            float b0 = bias[col], b1 = bias[col + 1];
            #pragma unroll
            for (int half = 0; half < 2; half++) {
                float v0 = (acc[nb][2 * half]     + b0) * sc;
                float v1 = (acc[nb][2 * half + 1] + b1) * sc;
                size_t oi = (hb * NS + s0 + r0g + half * 8) * DK + col;
                *(uint32_t*)(dq + oi) = pack2h(v0, v1);
            }
        }
    } else {
        __half* Vst = (__half*)(sm);   // 64 x 136 halves
        __syncthreads();
        #pragma unroll
        for (int nb = 0; nb < 8; nb++) {
            int col = 8 * nb + 2 * t4;
            float b0 = bias[col], b1 = bias[col + 1];
            #pragma unroll
            for (int half = 0; half < 2; half++) {
                float v0 = acc[nb][2 * half]     + b0;
                float v1 = acc[nb][2 * half + 1] + b1;
                int srow = r0g + half * 8;
                Vst[col * 136 + srow]       = __float2half_rn(v0);
                Vst[(col + 1) * 136 + srow] = __float2half_rn(v1);
            }
        }
        __syncthreads();
        const int n = tid >> 2, seg = tid & 3;
        const __half* sr = Vst + n * 136 + seg * 32;
        __half* ds = g_v16 + (hb * DK + n) * NS + s0 + seg * 32;
        #pragma unroll
        for (int u = 0; u < 4; u++)
            *(uint4*)(ds + u * 8) = *(const uint4*)(sr + u * 8);
    }
}

// ---------------------------------------------------------------------------
// attn: m32 warp tiles, 3-stage K/V rings, one sync/tile (R13 structure).
// ---------------------------------------------------------------------------
#define ARR_B  (64 * PITCH)              // 9216
#define Q_B    (128 * PITCH)             // 18432
#define SM_Q   0
#define SM_K   Q_B                       // 3 stages
#define SM_V   (Q_B + 3 * ARR_B)         // 3 stages
#define ATT_SMEM (Q_B + 6 * ARR_B)       // 73728
#define NT (NS / 64)

__global__ __launch_bounds__(128, 2) void attn_mma(float* __restrict__ out)
{
    extern __shared__ char sm[];
    const uint32_t sbase = smem_u32(sm);
    const int tid = threadIdx.x, wid = tid >> 5, lane = tid & 31;
    const int qt = blockIdx.x, h = blockIdx.y, b = blockIdx.z;
    const size_t hb = (size_t)b * NH + h;

    const __half* qp = g_q16 + hb * NS * DK;
    const __half* kp = g_k16 + hb * NS * DK;
    const __half* vp = g_v16 + hb * DK * NS;

    auto loadK = [&](int st, int t) {
        if (t < NT) {
            int j0 = t * 64;
            #pragma unroll
            for (int i = 0; i < 4; i++) {
                int idx = tid + i * 128;
                int row = idx >> 3, ch = idx & 7;
                uint32_t dst = sbase + SM_K + st * ARR_B + row * PITCH + ch * 16;
                cpa16(dst, kp + (size_t)(j0 + row) * DK + ch * 8);
            }
        }
        cp_commit();
    };
    auto loadV = [&](int st, int t) {
        if (t < NT) {
            int j0 = t * 64;
            #pragma unroll
            for (int i = 0; i < 4; i++) {
                int idx = tid + i * 128;
                int row = idx >> 3, ch = idx & 7;
                uint32_t dst = sbase + SM_V + st * ARR_B + row * PITCH + ch * 16;
                cpa16(dst, vp + (size_t)row * NS + j0 + ch * 8);
            }
        }
        cp_commit();
    };

    // prologue: G0 = Q + K0 + V0; then K1 (G1), V1 (G2)
    #pragma unroll
    for (int i = 0; i < 8; i++) {
        int idx = tid + i * 128;
        int row = idx >> 3, ch = idx & 7;
        cpa16(sbase + SM_Q + row * PITCH + ch * 16, qp + (size_t)(qt * 128 + row) * DK + ch * 8);
    }
    #pragma unroll
    for (int i = 0; i < 4; i++) {
        int idx = tid + i * 128;
        int row = idx >> 3, ch = idx & 7;
        cpa16(sbase + SM_K + row * PITCH + ch * 16, kp + (size_t)row * DK + ch * 8);
        cpa16(sbase + SM_V + row * PITCH + ch * 16, vp + (size_t)row * NS + ch * 8);
    }
    cp_commit();            // G0
    loadK(1, 1);            // G1
    loadV(1, 1);            // G2

    cp_wait<2>();
    __syncthreads();

    uint32_t qf[4][8];
    {
        const int qr = wid * 32 + (lane & 15);
        const int qcol8 = 8 * (lane >> 4);
        #pragma unroll
        for (int kb = 0; kb < 4; kb++) {
            uint32_t off0 = (uint32_t)qr * PITCH + (uint32_t)(kb * 16 + qcol8) * 2;
            uint32_t off1 = (uint32_t)(qr + 16) * PITCH + (uint32_t)(kb * 16 + qcol8) * 2;
            ldsm_x4(qf[kb][0], qf[kb][1], qf[kb][2], qf[kb][3], sbase + SM_Q + off0);
            ldsm_x4(qf[kb][4], qf[kb][5], qf[kb][6], qf[kb][7], sbase + SM_Q + off1);
        }
    }

    const int brow = (lane & 7) + ((lane >> 4) << 3);
    const int bcol8 = 8 * ((lane >> 3) & 1);

    float oacc[2][8][4] = {};
    float lacc[2][4] = {};
    float sacc[2][8][4];

    auto kstg = [&](int st) -> uint32_t { return sbase + SM_K + (uint32_t)st * ARR_B; };
    auto vstg = [&](int st) -> uint32_t { return sbase + SM_V + (uint32_t)st * ARR_B; };

    #pragma unroll 1
    for (int j = 0; j < NT; j++) {
        const int st = j % 3;
        cp_wait<2>();
        __syncthreads();
        loadK((j + 2) % 3, j + 2);
        loadV((j + 2) % 3, j + 2);

        // ---- S = Q.K^T ----
        {
            const uint32_t stg = kstg(st);
            #pragma unroll
            for (int kb = 0; kb < 4; kb++) {
                #pragma unroll
                for (int ng = 0; ng < 4; ng++) {
                    uint32_t off = (uint32_t)(ng * 16 + brow) * PITCH + (uint32_t)(kb * 16 + bcol8) * 2;
                    uint32_t k0, k1, k2, k3;
                    ldsm_x4(k0, k1, k2, k3, stg + off);
                    if (kb == 0) {
                        mma_hf_z(sacc[0][2 * ng],     qf[kb],     k0, k1);
                        mma_hf_z(sacc[0][2 * ng + 1], qf[kb],     k2, k3);
                        mma_hf_z(sacc[1][2 * ng],     qf[kb] + 4, k0, k1);
                        mma_hf_z(sacc[1][2 * ng + 1], qf[kb] + 4, k2, k3);
                    } else {
                        mma_hf(sacc[0][2 * ng],     qf[kb],     k0, k1);
                        mma_hf(sacc[0][2 * ng + 1], qf[kb],     k2, k3);
                        mma_hf(sacc[1][2 * ng],     qf[kb] + 4, k0, k1);
                        mma_hf(sacc[1][2 * ng + 1], qf[kb] + 4, k2, k3);
                    }
                }
            }
        }

        // ---- softmax + O += P.V ----
        {
            #pragma unroll
            for (int mh2 = 0; mh2 < 2; mh2++)
                #pragma unroll
                for (int nb = 0; nb < 8; nb++) {
                    sacc[mh2][nb][0] = ex2f(sacc[mh2][nb][0]);
                    sacc[mh2][nb][1] = ex2f(sacc[mh2][nb][1]);
                    sacc[mh2][nb][2] = ex2f(sacc[mh2][nb][2]);
                    sacc[mh2][nb][3] = ex2f(sacc[mh2][nb][3]);
                }
            const uint32_t stg = vstg(st);
            #pragma unroll
            for (int kb = 0; kb < 4; kb++) {
                uint32_t a0[4], a1[4];
                #pragma unroll
                for (int q2 = 0; q2 < 2; q2++) {
                    const float* c0 = sacc[0][2 * kb + q2];
                    const float* c1 = sacc[1][2 * kb + q2];
                    a0[q2 * 2 + 0] = pack2h(c0[0], c0[1]);
                    a0[q2 * 2 + 1] = pack2h(c0[2], c0[3]);
                    a1[q2 * 2 + 0] = pack2h(c1[0], c1[1]);
                    a1[q2 * 2 + 1] = pack2h(c1[2], c1[3]);
                }
                mma_hf(lacc[0], a0, ONES2, ONES2);
                mma_hf(lacc[1], a1, ONES2, ONES2);
                #pragma unroll
                for (int ng = 0; ng < 4; ng++) {
                    uint32_t off = (uint32_t)(ng * 16 + brow) * PITCH + (uint32_t)(kb * 16 + bcol8) * 2;
                    uint32_t v0, v1, v2, v3;
                    ldsm_x4(v0, v1, v2, v3, stg + off);
                    mma_hf(oacc[0][2 * ng],     a0, v0, v1);
                    mma_hf(oacc[0][2 * ng + 1], a0, v2, v3);
                    mma_hf(oacc[1][2 * ng],     a1, v0, v1);
                    mma_hf(oacc[1][2 * ng + 1], a1, v2, v3);
                }
            }
        }
    }
    cp_wait<0>();

    // epilogue
    const int g = lane >> 2, t4 = lane & 3;
    const int rbase = qt * 128 + wid * 32 + g;
    float inv[4] = {1.f / lacc[0][0], 1.f / lacc[0][2], 1.f / lacc[1][0], 1.f / lacc[1][2]};
    #pragma unroll
    for (int rg = 0; rg < 4; rg++) {
        const int mh2 = rg >> 1, lo = rg & 1;
        float* op = out + ((size_t)b * NS + rbase + mh2 * 16 + lo * 8) * (NH * DK) + h * DK;
        #pragma unroll
        for (int nb = 0; nb < 8; nb++) {
            int col = 8 * nb + 2 * t4;
            *(float2*)(op + col) = make_float2(oacc[mh2][nb][2 * lo]     * inv[rg],
                                               oacc[mh2][nb][2 * lo + 1] * inv[rg]);
        }
    }
}

extern "C" void kernel_launch(void* const* d_in, const int* in_sizes, int n_in,
                              void* d_out, int out_size)
{
    const float* x  = (const float*)d_in[0];
    const float* Wq = (const float*)d_in[1];
    const float* Wk = (const float*)d_in[2];
    const float* Wv = (const float*)d_in[3];
    const float* bq = (const float*)d_in[4];
    const float* bk = (const float*)d_in[5];
    const float* bv = (const float*)d_in[6];
    float* out = (float*)d_out;

    split_x<<<(NB * NS * ND) / 1024, 256>>>(x);
    split_w<<<24, 256>>>(Wq, Wk, Wv);

    cudaFuncSetAttribute(proj_mma, cudaFuncAttributeMaxDynamicSharedMemorySize, PJ_SMEM);
    dim3 pgrid(NS / 128, 24, NB);
    proj_mma<<<pgrid, 256, PJ_SMEM>>>(bq, bk, bv);

    cudaFuncSetAttribute(attn_mma, cudaFuncAttributeMaxDynamicSharedMemorySize, ATT_SMEM);
    dim3 agrid(NS / 128, NH, NB);
    attn_mma<<<agrid, 128, ATT_SMEM>>>(out);
}